// round 1
// baseline (speedup 1.0000x reference)
#include <cuda_runtime.h>
#include <cstddef>

// ---------------------------------------------------------------------------
// Problem constants (match dataset shapes; runtime dims derived from in_sizes)
// ---------------------------------------------------------------------------
#define MAXN  100000
#define MAXE  200000
#define MAXC5 30000
#define MAXC6 30000
#define MAXC  (MAXC5 + MAXC6)
#define MAXR  (5*MAXC5 + 6*MAXC6)   // 330000

// ---------------------------------------------------------------------------
// Scratch (device globals; no allocation anywhere)
// ---------------------------------------------------------------------------
__device__ float g_edge_h[MAXE*128];   // relu([lift_ne|edge] @ ne_l1_W)
__device__ float g_S     [MAXC*128];   // per-cycle 2*sum(edge_rep) (g11 sum)
__device__ float g_lvl_ne[MAXN*128];   // scatter of edge_h to nodes
__device__ float g_lvl   [MAXR*128];   // relu([lift|cyc_rep] @ ec_l1_W)
__device__ float g_lvl_ec[MAXE*128];   // cycle_to_edge(lvl)
__device__ float g_inter [MAXE*256];   // cycle_to_edge(cyc_rep)
__device__ float g_eo1   [MAXE*128];   // edge_out_1
__device__ float g_eo2   [MAXE*128];   // edge_out_2
__device__ int   g_ei [MAXR];          // edge index of row r
__device__ int   g_ep [MAXR];          // edge index of prev position in cycle
__device__ int   g_rn [MAXR];          // row index of next position in cycle
__device__ int   g_cid[MAXR];          // global cycle id of row r

// ---------------------------------------------------------------------------
// Small helpers
// ---------------------------------------------------------------------------
__device__ __forceinline__ float4 ld4(const float* p){ return *reinterpret_cast<const float4*>(p); }
__device__ __forceinline__ float4 add4(float4 a, float4 b){ return make_float4(a.x+b.x, a.y+b.y, a.z+b.z, a.w+b.w); }
__device__ __forceinline__ float4 axpy4(float c, float4 a, float4 b){
  return make_float4(fmaf(c,a.x,b.x), fmaf(c,a.y,b.y), fmaf(c,a.z,b.z), fmaf(c,a.w,b.w));
}
__device__ __forceinline__ float4 scal4(float c, float4 a){ return make_float4(c*a.x, c*a.y, c*a.z, c*a.w); }

// ---------------------------------------------------------------------------
// Per-row metadata for cycle rows (r in [0, R))
// ---------------------------------------------------------------------------
__global__ void meta_k(const int* __restrict__ c5, const int* __restrict__ c6,
                       int C5, int C6, int R,
                       int* ei, int* ep, int* rn, int* cid)
{
  int r = blockIdx.x*blockDim.x + threadIdx.x;
  if (r >= R) return;
  int base5 = 5*C5;
  if (r < base5){
    int c = r/5, i = r - c*5;
    ei [r] = c5[c*5 + i];
    ep [r] = c5[c*5 + (i+4)%5];
    rn [r] = c*5 + (i+1)%5;
    cid[r] = c;
  } else {
    int rr = r - base5;
    int c = rr/6, i = rr - c*6;
    ei [r] = c6[c*6 + i];
    ep [r] = c6[c*6 + (i+5)%6];
    rn [r] = base5 + c*6 + (i+1)%6;
    cid[r] = C5 + c;
  }
}

// Per-cycle edge sum: S[c] = 2 * sum_i edge_rep[edges(c,i)]
__global__ void sum_k(const float* __restrict__ edge,
                      const int* __restrict__ c5, const int* __restrict__ c6,
                      int C5, float* __restrict__ S)
{
  int c = blockIdx.x, t = threadIdx.x;
  float s = 0.f;
  if (c < C5){
    const int* e = c5 + (size_t)c*5;
    #pragma unroll
    for (int i=0;i<5;i++) s += edge[(size_t)e[i]*128 + t];
  } else {
    const int* e = c6 + (size_t)(c - C5)*6;
    #pragma unroll
    for (int i=0;i<6;i++) s += edge[(size_t)e[i]*128 + t];
  }
  S[(size_t)c*128 + t] = 2.0f*s;
}

// cycle->edge scatter of lvl (128ch) and cyc_rep (256ch) in one pass
__global__ void scatter_k(const float* __restrict__ lvl, const float* __restrict__ cyc,
                          const int* __restrict__ ei, const int* __restrict__ rn,
                          float* __restrict__ lvl_ec, float* __restrict__ inter)
{
  int r = blockIdx.x, t = threadIdx.x;
  int e = ei[r], r2 = rn[r];
  float v = lvl[(size_t)r*128 + t] + lvl[(size_t)r2*128 + t];
  atomicAdd(&lvl_ec[(size_t)e*128 + t], v);
  float w0 = cyc[(size_t)r*256 +        t] + cyc[(size_t)r2*256 +        t];
  float w1 = cyc[(size_t)r*256 + 128 +  t] + cyc[(size_t)r2*256 + 128 +  t];
  atomicAdd(&inter[(size_t)e*256 +       t], w0);
  atomicAdd(&inter[(size_t)e*256 + 128 + t], w1);
}

// ---------------------------------------------------------------------------
// Fused GEMM: out[r][n] = relu( sum_k A(r,k) * B[k][n] )
// A(r,k) is built on-the-fly per mode (gathers / affine combines).
// BM=BN=128, BK=16, 256 threads, 8x8 per thread.
// ---------------------------------------------------------------------------
#define BM 128
#define BN 128
#define BK 16

struct GemmArgs {
  const float* B;          // weight, row-major [K][ldb]
  float*       out;        // output base
  float*       aux;        // mode 1: lvl_ne scatter target
  const float* a0; const float* a1; const float* a2;
  const int*   idx0; const int* idx1; const int* idx2;
  const float* sp0; const float* sp1;   // scalar eps pointers (may be null)
  int M, K, ldb, ldo;
};

// Modes:
// 1: A=[node[u]+node[v] | edge]            (K=256)  epi: write edge_h + atomic scatter to lvl_ne
// 2: A=c0*node + lvl_ne                    (K=128)
// 3: A=c0*edge_h + node[u]+node[v]         (K=128)
// 4: A=[edge[ei]+edge[ep] | S[c] | cyc[r]] (K=512)
// 5: A=c0*edge + c1*lvl_ec                 (K=128)
// 6: A=c0*(int[ei]+int[ep]) + ([edge[ei]+edge[ep] | S[c]])   (K=256)
// 7: A=[eo1 | eo2]                         (K=256)
template<int MODE>
__device__ __forceinline__ void loadA(const GemmArgs& g, int r, int k, bool valid,
                                      float c0, float c1, float4& o0, float4& o1)
{
  if (!valid){ o0 = make_float4(0,0,0,0); o1 = o0; return; }
  if constexpr (MODE == 1){
    if (k < 128){
      int u = g.idx0[2*r], v = g.idx0[2*r+1];
      const float* pu = g.a0 + (size_t)u*128 + k;
      const float* pv = g.a0 + (size_t)v*128 + k;
      o0 = add4(ld4(pu), ld4(pv)); o1 = add4(ld4(pu+4), ld4(pv+4));
    } else {
      const float* p = g.a1 + (size_t)r*128 + (k-128);
      o0 = ld4(p); o1 = ld4(p+4);
    }
  } else if constexpr (MODE == 2){
    const float* p0 = g.a0 + (size_t)r*128 + k;
    const float* p1 = g.a1 + (size_t)r*128 + k;
    o0 = axpy4(c0, ld4(p0), ld4(p1)); o1 = axpy4(c0, ld4(p0+4), ld4(p1+4));
  } else if constexpr (MODE == 3){
    int u = g.idx0[2*r], v = g.idx0[2*r+1];
    const float* ph = g.a0 + (size_t)r*128 + k;
    const float* pu = g.a1 + (size_t)u*128 + k;
    const float* pv = g.a1 + (size_t)v*128 + k;
    o0 = axpy4(c0, ld4(ph),   add4(ld4(pu),   ld4(pv)));
    o1 = axpy4(c0, ld4(ph+4), add4(ld4(pu+4), ld4(pv+4)));
  } else if constexpr (MODE == 4){
    if (k < 128){
      int ei = g.idx0[r], ep = g.idx1[r];
      const float* p0 = g.a0 + (size_t)ei*128 + k;
      const float* p1 = g.a0 + (size_t)ep*128 + k;
      o0 = add4(ld4(p0), ld4(p1)); o1 = add4(ld4(p0+4), ld4(p1+4));
    } else if (k < 256){
      int c = g.idx2[r];
      const float* p = g.a1 + (size_t)c*128 + (k-128);
      o0 = ld4(p); o1 = ld4(p+4);
    } else {
      const float* p = g.a2 + (size_t)r*256 + (k-256);
      o0 = ld4(p); o1 = ld4(p+4);
    }
  } else if constexpr (MODE == 5){
    const float* p0 = g.a0 + (size_t)r*128 + k;
    const float* p1 = g.a1 + (size_t)r*128 + k;
    o0 = add4(scal4(c0, ld4(p0)),   scal4(c1, ld4(p1)));
    o1 = add4(scal4(c0, ld4(p0+4)), scal4(c1, ld4(p1+4)));
  } else if constexpr (MODE == 6){
    int ei = g.idx0[r], ep = g.idx1[r];
    const float* p0 = g.a0 + (size_t)ei*256 + k;
    const float* p1 = g.a0 + (size_t)ep*256 + k;
    float4 b0 = add4(ld4(p0),   ld4(p1));
    float4 b1 = add4(ld4(p0+4), ld4(p1+4));
    float4 l0, l1;
    if (k < 128){
      const float* q0 = g.a1 + (size_t)ei*128 + k;
      const float* q1 = g.a1 + (size_t)ep*128 + k;
      l0 = add4(ld4(q0), ld4(q1)); l1 = add4(ld4(q0+4), ld4(q1+4));
    } else {
      int c = g.idx2[r];
      const float* q = g.a2 + (size_t)c*128 + (k-128);
      l0 = ld4(q); l1 = ld4(q+4);
    }
    o0 = axpy4(c0, b0, l0); o1 = axpy4(c0, b1, l1);
  } else { // MODE 7
    const float* p = (k < 128) ? (g.a0 + (size_t)r*128 + k)
                               : (g.a1 + (size_t)r*128 + (k-128));
    o0 = ld4(p); o1 = ld4(p+4);
  }
}

template<int MODE>
__global__ void __launch_bounds__(256, 2) gemm_k(GemmArgs g)
{
  __shared__ float As[BK][BM];
  __shared__ float Bs[BK][BN];

  const int tid  = threadIdx.x;
  const int row0 = blockIdx.y * BM;
  const int col0 = blockIdx.x * BN;

  // A-tile load mapping: 2 threads per row, 8 consecutive k each
  const int ar  = tid >> 1;
  const int ak8 = (tid & 1) * 8;
  const int r   = row0 + ar;
  const bool vrow = (r < g.M);

  // B-tile load mapping: tid*8 linear over 16x128
  const int bk = tid >> 4;
  const int bn = (tid & 15) * 8;

  // compute mapping
  const int tx = tid & 15;   // output col group
  const int ty = tid >> 4;   // output row group

  float c0 = g.sp0 ? (1.0f + *g.sp0) : 1.0f;
  float c1 = g.sp1 ? (1.0f + *g.sp1) : 1.0f;

  float acc[8][8];
  #pragma unroll
  for (int i=0;i<8;i++)
    #pragma unroll
    for (int j=0;j<8;j++) acc[i][j] = 0.f;

  const int kIters = g.K / BK;
  for (int kt = 0; kt < kIters; kt++){
    const int k0 = kt * BK;
    float4 av0, av1;
    loadA<MODE>(g, r, k0 + ak8, vrow, c0, c1, av0, av1);
    const float* bp = g.B + (size_t)(k0 + bk) * g.ldb + col0 + bn;
    float4 bv0 = ld4(bp), bv1 = ld4(bp + 4);

    __syncthreads();
    As[ak8+0][ar]=av0.x; As[ak8+1][ar]=av0.y; As[ak8+2][ar]=av0.z; As[ak8+3][ar]=av0.w;
    As[ak8+4][ar]=av1.x; As[ak8+5][ar]=av1.y; As[ak8+6][ar]=av1.z; As[ak8+7][ar]=av1.w;
    *reinterpret_cast<float4*>(&Bs[bk][bn])     = bv0;
    *reinterpret_cast<float4*>(&Bs[bk][bn + 4]) = bv1;
    __syncthreads();

    #pragma unroll
    for (int kk = 0; kk < BK; kk++){
      float4 x0 = *reinterpret_cast<const float4*>(&As[kk][ty*8]);
      float4 x1 = *reinterpret_cast<const float4*>(&As[kk][ty*8+4]);
      float4 y0 = *reinterpret_cast<const float4*>(&Bs[kk][tx*8]);
      float4 y1 = *reinterpret_cast<const float4*>(&Bs[kk][tx*8+4]);
      float xa[8] = {x0.x,x0.y,x0.z,x0.w,x1.x,x1.y,x1.z,x1.w};
      float yb[8] = {y0.x,y0.y,y0.z,y0.w,y1.x,y1.y,y1.z,y1.w};
      #pragma unroll
      for (int i=0;i<8;i++)
        #pragma unroll
        for (int j=0;j<8;j++)
          acc[i][j] = fmaf(xa[i], yb[j], acc[i][j]);
    }
  }

  // epilogue: relu, store, optional scatter
  #pragma unroll
  for (int i=0;i<8;i++){
    int rr = row0 + ty*8 + i;
    if (rr < g.M){
      float vals[8];
      #pragma unroll
      for (int j=0;j<8;j++) vals[j] = fmaxf(acc[i][j], 0.0f);
      size_t off = (size_t)rr * g.ldo + col0 + tx*8;
      *reinterpret_cast<float4*>(g.out + off)     = make_float4(vals[0],vals[1],vals[2],vals[3]);
      *reinterpret_cast<float4*>(g.out + off + 4) = make_float4(vals[4],vals[5],vals[6],vals[7]);
      if constexpr (MODE == 1){
        int u = g.idx0[2*rr], v = g.idx0[2*rr+1];
        float* pa = g.aux + (size_t)u*128 + col0 + tx*8;
        float* pb = g.aux + (size_t)v*128 + col0 + tx*8;
        #pragma unroll
        for (int j=0;j<8;j++){
          atomicAdd(pa + j, vals[j]);
          atomicAdd(pb + j, vals[j]);
        }
      }
    }
  }
}

// ---------------------------------------------------------------------------
// Launcher
// ---------------------------------------------------------------------------
extern "C" void kernel_launch(void* const* d_in, const int* in_sizes, int n_in,
                              void* d_out, int out_size)
{
  const float* node      = (const float*)d_in[0];
  const float* edge      = (const float*)d_in[1];
  const float* cyc       = (const float*)d_in[2];
  const float* ne_lift_W = (const float*)d_in[3];
  const float* ne_l1_W   = (const float*)d_in[4];
  const float* ne_l2_W   = (const float*)d_in[5];
  const float* ec_lift_W = (const float*)d_in[6];
  const float* ec_l1_W   = (const float*)d_in[7];
  const float* ec_l2_W   = (const float*)d_in[8];
  const float* mlp_W     = (const float*)d_in[9];
  const float* eps1      = (const float*)d_in[10];
  const float* eps2      = (const float*)d_in[11];
  const float* e11       = (const float*)d_in[12];
  const float* e12       = (const float*)d_in[13];
  const float* e2        = (const float*)d_in[14];
  const int*   edge_nodes= (const int*)  d_in[15];
  const int*   c5        = (const int*)  d_in[16];
  const int*   c6        = (const int*)  d_in[17];

  const int N  = in_sizes[0]  / 128;
  const int E  = in_sizes[1]  / 128;
  const int C5 = in_sizes[16] / 5;
  const int C6 = in_sizes[17] / 6;
  const int R  = 5*C5 + 6*C6;
  float* out = (float*)d_out;

  float *edge_h, *S, *lvl_ne, *lvl, *lvl_ec, *inter, *eo1, *eo2;
  int *ei, *ep, *rn, *cid;
  cudaGetSymbolAddress((void**)&edge_h, g_edge_h);
  cudaGetSymbolAddress((void**)&S,      g_S);
  cudaGetSymbolAddress((void**)&lvl_ne, g_lvl_ne);
  cudaGetSymbolAddress((void**)&lvl,    g_lvl);
  cudaGetSymbolAddress((void**)&lvl_ec, g_lvl_ec);
  cudaGetSymbolAddress((void**)&inter,  g_inter);
  cudaGetSymbolAddress((void**)&eo1,    g_eo1);
  cudaGetSymbolAddress((void**)&eo2,    g_eo2);
  cudaGetSymbolAddress((void**)&ei,  g_ei);
  cudaGetSymbolAddress((void**)&ep,  g_ep);
  cudaGetSymbolAddress((void**)&rn,  g_rn);
  cudaGetSymbolAddress((void**)&cid, g_cid);

  cudaMemsetAsync(lvl_ne, 0, (size_t)N*128*sizeof(float), 0);
  cudaMemsetAsync(lvl_ec, 0, (size_t)E*128*sizeof(float), 0);
  cudaMemsetAsync(inter,  0, (size_t)E*256*sizeof(float), 0);

  meta_k<<<(R + 255)/256, 256>>>(c5, c6, C5, C6, R, ei, ep, rn, cid);
  sum_k<<<C5 + C6, 128>>>(edge, c5, c6, C5, S);

  // G1: edge_h = relu([node[u]+node[v] | edge] @ ne_l1_W); scatter to lvl_ne
  {
    GemmArgs a{}; a.B = ne_l1_W; a.ldb = 128; a.M = E; a.K = 256;
    a.out = edge_h; a.ldo = 128; a.aux = lvl_ne;
    a.a0 = node; a.a1 = edge; a.idx0 = edge_nodes;
    gemm_k<1><<<dim3(1, (E + BM - 1)/BM), 256>>>(a);
  }
  // G2: node_out = relu(((1+eps1)*node + lvl_ne) @ ne_l2_W)  -> d_out[0:]
  {
    GemmArgs a{}; a.B = ne_l2_W; a.ldb = 128; a.M = N; a.K = 128;
    a.out = out; a.ldo = 128;
    a.a0 = node; a.a1 = lvl_ne; a.sp0 = eps1;
    gemm_k<2><<<dim3(1, (N + BM - 1)/BM), 256>>>(a);
  }
  // G3: edge_out_1 = relu(((1+eps2)*edge_h + node[u]+node[v]) @ ne_lift_W)
  {
    GemmArgs a{}; a.B = ne_lift_W; a.ldb = 128; a.M = E; a.K = 128;
    a.out = eo1; a.ldo = 128;
    a.a0 = edge_h; a.a1 = node; a.idx0 = edge_nodes; a.sp0 = eps2;
    gemm_k<3><<<dim3(1, (E + BM - 1)/BM), 256>>>(a);
  }
  // G4: lvl = relu([e2c | S | cyc_rep] @ ec_l1_W)
  {
    GemmArgs a{}; a.B = ec_l1_W; a.ldb = 128; a.M = R; a.K = 512;
    a.out = lvl; a.ldo = 128;
    a.a0 = edge; a.a1 = S; a.a2 = cyc;
    a.idx0 = ei; a.idx1 = ep; a.idx2 = cid;
    gemm_k<4><<<dim3(1, (R + BM - 1)/BM), 256>>>(a);
  }
  // scatter: lvl_ec += cycle_to_edge(lvl); inter += cycle_to_edge(cyc_rep)
  scatter_k<<<R, 128>>>(lvl, cyc, ei, rn, lvl_ec, inter);

  // G5: edge_out_2 = relu(((1+e11)*edge + (1+e12)*lvl_ec) @ ec_l2_W)
  {
    GemmArgs a{}; a.B = ec_l2_W; a.ldb = 128; a.M = E; a.K = 128;
    a.out = eo2; a.ldo = 128;
    a.a0 = edge; a.a1 = lvl_ec; a.sp0 = e11; a.sp1 = e12;
    gemm_k<5><<<dim3(1, (E + BM - 1)/BM), 256>>>(a);
  }
  // G6: cycle_out = relu(((1+e2)*lin + lift) @ ec_lift_W)  -> d_out cycle section
  {
    GemmArgs a{}; a.B = ec_lift_W; a.ldb = 256; a.M = R; a.K = 256;
    a.out = out + (size_t)(N + E)*128; a.ldo = 256;
    a.a0 = inter; a.a1 = edge; a.a2 = S;
    a.idx0 = ei; a.idx1 = ep; a.idx2 = cid; a.sp0 = e2;
    gemm_k<6><<<dim3(2, (R + BM - 1)/BM), 256>>>(a);
  }
  // G7: edge_out = relu([eo1 | eo2] @ mlp_W)  -> d_out edge section
  {
    GemmArgs a{}; a.B = mlp_W; a.ldb = 128; a.M = E; a.K = 256;
    a.out = out + (size_t)N*128; a.ldo = 128;
    a.a0 = eo1; a.a1 = eo2;
    gemm_k<7><<<dim3(1, (E + BM - 1)/BM), 256>>>(a);
  }
}

// round 3
// speedup vs baseline: 2.1035x; 2.1035x over previous
#include <cuda_runtime.h>
#include <cstddef>
#include <cstdint>

// ---------------------------------------------------------------------------
// Problem constants
// ---------------------------------------------------------------------------
#define MAXN  100000
#define MAXE  200000
#define MAXC5 30000
#define MAXC6 30000
#define MAXC  (MAXC5 + MAXC6)
#define MAXR  (5*MAXC5 + 6*MAXC6)   // 330000

// ---------------------------------------------------------------------------
// Scratch (device globals; no allocation anywhere)
// ---------------------------------------------------------------------------
__device__ float g_edge_h[MAXE*128];
__device__ float g_S     [MAXC*128];
__device__ float g_lvl_ne[MAXN*128];
__device__ float g_lvl   [MAXR*128];
__device__ float g_lvl_ec[MAXE*128];
__device__ float g_inter [MAXE*256];
__device__ float g_eo1   [MAXE*128];
__device__ float g_eo2   [MAXE*128];
__device__ int   g_ei [MAXR];
__device__ int   g_ep [MAXR];
__device__ int   g_rn [MAXR];
__device__ int   g_cid[MAXR];
// transposed weights Wt[n][k] (K contiguous)
__device__ float g_Wt[245760];
#define WT_NE_L1   0
#define WT_NE_L2   32768
#define WT_NE_LIFT 49152
#define WT_EC_L1   65536
#define WT_EC_L2   131072
#define WT_EC_LIFT 147456
#define WT_MLP     212992

// ---------------------------------------------------------------------------
// Helpers
// ---------------------------------------------------------------------------
__device__ __forceinline__ float to_tf32(float x){
  float y; asm("cvt.rna.tf32.f32 %0, %1;" : "=f"(y) : "f"(x)); return y;
}
__device__ __forceinline__ float4 ld4(const float* p){ return *reinterpret_cast<const float4*>(p); }
__device__ __forceinline__ float4 add4(float4 a, float4 b){ return make_float4(a.x+b.x, a.y+b.y, a.z+b.z, a.w+b.w); }
__device__ __forceinline__ float4 axpy4(float c, float4 a, float4 b){
  return make_float4(fmaf(c,a.x,b.x), fmaf(c,a.y,b.y), fmaf(c,a.z,b.z), fmaf(c,a.w,b.w));
}
__device__ __forceinline__ float4 scal4(float c, float4 a){ return make_float4(c*a.x, c*a.y, c*a.z, c*a.w); }
__device__ __forceinline__ float4 tf4(float4 a){
  return make_float4(to_tf32(a.x), to_tf32(a.y), to_tf32(a.z), to_tf32(a.w));
}
__device__ __forceinline__ void mma_tf32(float* c, const uint32_t* a, const uint32_t* b){
  asm volatile(
    "mma.sync.aligned.m16n8k8.row.col.f32.tf32.tf32.f32 "
    "{%0,%1,%2,%3}, {%4,%5,%6,%7}, {%8,%9}, {%0,%1,%2,%3};"
    : "+f"(c[0]), "+f"(c[1]), "+f"(c[2]), "+f"(c[3])
    : "r"(a[0]), "r"(a[1]), "r"(a[2]), "r"(a[3]), "r"(b[0]), "r"(b[1]));
}

// ---------------------------------------------------------------------------
// Aux kernels
// ---------------------------------------------------------------------------
__global__ void meta_k(const int* __restrict__ c5, const int* __restrict__ c6,
                       int C5, int C6, int R,
                       int* ei, int* ep, int* rn, int* cid)
{
  int r = blockIdx.x*blockDim.x + threadIdx.x;
  if (r >= R) return;
  int base5 = 5*C5;
  if (r < base5){
    int c = r/5, i = r - c*5;
    ei [r] = c5[c*5 + i];
    ep [r] = c5[c*5 + (i+4)%5];
    rn [r] = c*5 + (i+1)%5;
    cid[r] = c;
  } else {
    int rr = r - base5;
    int c = rr/6, i = rr - c*6;
    ei [r] = c6[c*6 + i];
    ep [r] = c6[c*6 + (i+5)%6];
    rn [r] = base5 + c*6 + (i+1)%6;
    cid[r] = C5 + c;
  }
}

__global__ void sum_k(const float* __restrict__ edge,
                      const int* __restrict__ c5, const int* __restrict__ c6,
                      int C5, float* __restrict__ S)
{
  int c = blockIdx.x, t = threadIdx.x;
  float s = 0.f;
  if (c < C5){
    const int* e = c5 + (size_t)c*5;
    #pragma unroll
    for (int i=0;i<5;i++) s += edge[(size_t)e[i]*128 + t];
  } else {
    const int* e = c6 + (size_t)(c - C5)*6;
    #pragma unroll
    for (int i=0;i<6;i++) s += edge[(size_t)e[i]*128 + t];
  }
  S[(size_t)c*128 + t] = 2.0f*s;
}

__global__ void scatter_k(const float* __restrict__ lvl, const float* __restrict__ cyc,
                          const int* __restrict__ ei, const int* __restrict__ rn,
                          float* __restrict__ lvl_ec, float* __restrict__ inter)
{
  int r = blockIdx.x, t = threadIdx.x;
  int e = ei[r], r2 = rn[r];
  float v = lvl[(size_t)r*128 + t] + lvl[(size_t)r2*128 + t];
  atomicAdd(&lvl_ec[(size_t)e*128 + t], v);
  float w0 = cyc[(size_t)r*256 +        t] + cyc[(size_t)r2*256 +        t];
  float w1 = cyc[(size_t)r*256 + 128 +  t] + cyc[(size_t)r2*256 + 128 +  t];
  atomicAdd(&inter[(size_t)e*256 +       t], w0);
  atomicAdd(&inter[(size_t)e*256 + 128 + t], w1);
}

// 32x32 tiled transpose: out[n*K+k] = in[k*N+n]
__global__ void transpose_k(const float* __restrict__ in, float* __restrict__ out,
                            int K, int N)
{
  __shared__ float t[32][33];
  int kb = blockIdx.y*32, nb = blockIdx.x*32;
  #pragma unroll
  for (int i=0;i<4;i++){
    int k = kb + threadIdx.y + i*8;
    t[threadIdx.y + i*8][threadIdx.x] = in[(size_t)k*N + nb + threadIdx.x];
  }
  __syncthreads();
  #pragma unroll
  for (int i=0;i<4;i++){
    int n = nb + threadIdx.y + i*8;
    out[(size_t)n*K + kb + threadIdx.x] = t[threadIdx.x][threadIdx.y + i*8];
  }
}

// ---------------------------------------------------------------------------
// Fused tensor-core GEMM (tf32 mma.sync): out = relu(A @ W), A built on the fly
// Tile: 128(M) x 128(N) x 32(K-chunk). 256 thr = 8 warps, warp tile 32x64.
// ---------------------------------------------------------------------------
struct GemmArgs {
  const float* B;          // Wt base [Ntotal][K] (K contiguous)
  float*       out;
  float*       aux;        // mode 1: lvl_ne scatter target
  const float* a0; const float* a1; const float* a2;
  const int*   idx0; const int* idx1; const int* idx2;
  const float* sp0; const float* sp1;
  int M, K, ldo;
};

// Modes (A row construction, 8 floats at (r, k..k+8)):
// 1: [node[u]+node[v] | edge]            K=256   epi: + atomic scatter to lvl_ne
// 2: c0*node + lvl_ne                    K=128
// 3: c0*edge_h + node[u]+node[v]         K=128
// 4: [edge[ei]+edge[ep] | S[c] | cyc[r]] K=512
// 5: c0*edge + c1*lvl_ec                 K=128
// 6: c0*(int[ei]+int[ep]) + [edge[ei]+edge[ep] | S[c]]  K=256
// 7: [eo1 | eo2]                         K=256
template<int MODE>
__device__ __forceinline__ void loadA(const GemmArgs& g, int r, int k, bool valid,
                                      float c0, float c1, float4& o0, float4& o1)
{
  if (!valid){ o0 = make_float4(0,0,0,0); o1 = o0; return; }
  if constexpr (MODE == 1){
    if (k < 128){
      int u = g.idx0[2*r], v = g.idx0[2*r+1];
      const float* pu = g.a0 + (size_t)u*128 + k;
      const float* pv = g.a0 + (size_t)v*128 + k;
      o0 = add4(ld4(pu), ld4(pv)); o1 = add4(ld4(pu+4), ld4(pv+4));
    } else {
      const float* p = g.a1 + (size_t)r*128 + (k-128);
      o0 = ld4(p); o1 = ld4(p+4);
    }
  } else if constexpr (MODE == 2){
    const float* p0 = g.a0 + (size_t)r*128 + k;
    const float* p1 = g.a1 + (size_t)r*128 + k;
    o0 = axpy4(c0, ld4(p0), ld4(p1)); o1 = axpy4(c0, ld4(p0+4), ld4(p1+4));
  } else if constexpr (MODE == 3){
    int u = g.idx0[2*r], v = g.idx0[2*r+1];
    const float* ph = g.a0 + (size_t)r*128 + k;
    const float* pu = g.a1 + (size_t)u*128 + k;
    const float* pv = g.a1 + (size_t)v*128 + k;
    o0 = axpy4(c0, ld4(ph),   add4(ld4(pu),   ld4(pv)));
    o1 = axpy4(c0, ld4(ph+4), add4(ld4(pu+4), ld4(pv+4)));
  } else if constexpr (MODE == 4){
    if (k < 128){
      int ei = g.idx0[r], ep = g.idx1[r];
      const float* p0 = g.a0 + (size_t)ei*128 + k;
      const float* p1 = g.a0 + (size_t)ep*128 + k;
      o0 = add4(ld4(p0), ld4(p1)); o1 = add4(ld4(p0+4), ld4(p1+4));
    } else if (k < 256){
      int c = g.idx2[r];
      const float* p = g.a1 + (size_t)c*128 + (k-128);
      o0 = ld4(p); o1 = ld4(p+4);
    } else {
      const float* p = g.a2 + (size_t)r*256 + (k-256);
      o0 = ld4(p); o1 = ld4(p+4);
    }
  } else if constexpr (MODE == 5){
    const float* p0 = g.a0 + (size_t)r*128 + k;
    const float* p1 = g.a1 + (size_t)r*128 + k;
    o0 = add4(scal4(c0, ld4(p0)),   scal4(c1, ld4(p1)));
    o1 = add4(scal4(c0, ld4(p0+4)), scal4(c1, ld4(p1+4)));
  } else if constexpr (MODE == 6){
    int ei = g.idx0[r], ep = g.idx1[r];
    const float* p0 = g.a0 + (size_t)ei*256 + k;
    const float* p1 = g.a0 + (size_t)ep*256 + k;
    float4 b0 = add4(ld4(p0),   ld4(p1));
    float4 b1 = add4(ld4(p0+4), ld4(p1+4));
    float4 l0, l1;
    if (k < 128){
      const float* q0 = g.a1 + (size_t)ei*128 + k;
      const float* q1 = g.a1 + (size_t)ep*128 + k;
      l0 = add4(ld4(q0), ld4(q1)); l1 = add4(ld4(q0+4), ld4(q1+4));
    } else {
      int c = g.idx2[r];
      const float* q = g.a2 + (size_t)c*128 + (k-128);
      l0 = ld4(q); l1 = ld4(q+4);
    }
    o0 = axpy4(c0, b0, l0); o1 = axpy4(c0, b1, l1);
  } else { // MODE 7
    const float* p = (k < 128) ? (g.a0 + (size_t)r*128 + k)
                               : (g.a1 + (size_t)r*128 + (k-128));
    o0 = ld4(p); o1 = ld4(p+4);
  }
}

#define ASTRIDE 36   // padded row stride (floats) — conflict-free fragment loads

template<int MODE>
__global__ void __launch_bounds__(256, 2) mgemm_k(GemmArgs g)
{
  __shared__ float As[128][ASTRIDE];
  __shared__ float Bs[128][ASTRIDE];

  const int tid  = threadIdx.x;
  const int lane = tid & 31;
  const int wid  = tid >> 5;
  const int gq   = lane >> 2;     // group 0..7
  const int tig  = lane & 3;      // thread-in-group
  const int warp_m = wid >> 1, warp_n = wid & 1;
  const int m_base = warp_m * 32, n_base = warp_n * 64;
  const int row0 = blockIdx.y * 128;
  const int col0 = blockIdx.x * 128;

  // Loader mapping: 2 threads per row, 16 floats each
  const int ar   = tid >> 1;
  const int half = tid & 1;
  const int r    = row0 + ar;
  const bool vrow = (r < g.M);

  const float c0 = g.sp0 ? (1.0f + *g.sp0) : 1.0f;
  const float c1 = g.sp1 ? (1.0f + *g.sp1) : 1.0f;

  const float* bptr = g.B + (size_t)(col0 + ar) * g.K + half*16;

  float acc[2][8][4];
  #pragma unroll
  for (int mi=0;mi<2;mi++)
    #pragma unroll
    for (int ni=0;ni<8;ni++)
      #pragma unroll
      for (int i=0;i<4;i++) acc[mi][ni][i] = 0.f;

  const int nK = g.K >> 5;
  for (int kt = 0; kt < nK; kt++){
    const int k0 = kt * 32;
    float4 a0, a1, a2, a3;
    loadA<MODE>(g, r, k0 + half*16,     vrow, c0, c1, a0, a1);
    loadA<MODE>(g, r, k0 + half*16 + 8, vrow, c0, c1, a2, a3);
    float4 b0 = ld4(bptr + k0),     b1 = ld4(bptr + k0 + 4);
    float4 b2 = ld4(bptr + k0 + 8), b3 = ld4(bptr + k0 + 12);

    __syncthreads();
    {
      float* pa = &As[ar][half*16];
      *reinterpret_cast<float4*>(pa)      = tf4(a0);
      *reinterpret_cast<float4*>(pa + 4)  = tf4(a1);
      *reinterpret_cast<float4*>(pa + 8)  = tf4(a2);
      *reinterpret_cast<float4*>(pa + 12) = tf4(a3);
      float* pb = &Bs[ar][half*16];
      *reinterpret_cast<float4*>(pb)      = tf4(b0);
      *reinterpret_cast<float4*>(pb + 4)  = tf4(b1);
      *reinterpret_cast<float4*>(pb + 8)  = tf4(b2);
      *reinterpret_cast<float4*>(pb + 12) = tf4(b3);
    }
    __syncthreads();

    #pragma unroll
    for (int ks = 0; ks < 4; ks++){
      const int kk = ks * 8;
      uint32_t af[2][4];
      #pragma unroll
      for (int mi = 0; mi < 2; mi++){
        const int mrow = m_base + mi*16 + gq;
        af[mi][0] = __float_as_uint(As[mrow    ][kk + tig]);
        af[mi][1] = __float_as_uint(As[mrow + 8][kk + tig]);
        af[mi][2] = __float_as_uint(As[mrow    ][kk + tig + 4]);
        af[mi][3] = __float_as_uint(As[mrow + 8][kk + tig + 4]);
      }
      uint32_t bf[8][2];
      #pragma unroll
      for (int ni = 0; ni < 8; ni++){
        const int nrow = n_base + ni*8 + gq;
        bf[ni][0] = __float_as_uint(Bs[nrow][kk + tig]);
        bf[ni][1] = __float_as_uint(Bs[nrow][kk + tig + 4]);
      }
      #pragma unroll
      for (int mi = 0; mi < 2; mi++)
        #pragma unroll
        for (int ni = 0; ni < 8; ni++)
          mma_tf32(acc[mi][ni], af[mi], bf[ni]);
    }
  }

  // Epilogue: relu + store (+ mode-1 atomic scatter). c-frag rows gq / gq+8.
  #pragma unroll
  for (int mi = 0; mi < 2; mi++){
    #pragma unroll
    for (int rsel = 0; rsel < 2; rsel++){
      const int rr = row0 + m_base + mi*16 + gq + rsel*8;
      if (rr < g.M){
        int u = 0, v = 0;
        if constexpr (MODE == 1){ u = g.idx0[2*rr]; v = g.idx0[2*rr+1]; }
        #pragma unroll
        for (int ni = 0; ni < 8; ni++){
          const int cc = col0 + n_base + ni*8 + 2*tig;
          float v0 = fmaxf(acc[mi][ni][rsel*2],     0.0f);
          float v1 = fmaxf(acc[mi][ni][rsel*2 + 1], 0.0f);
          *reinterpret_cast<float2*>(g.out + (size_t)rr * g.ldo + cc) = make_float2(v0, v1);
          if constexpr (MODE == 1){
            atomicAdd(g.aux + (size_t)u*128 + cc,     v0);
            atomicAdd(g.aux + (size_t)u*128 + cc + 1, v1);
            atomicAdd(g.aux + (size_t)v*128 + cc,     v0);
            atomicAdd(g.aux + (size_t)v*128 + cc + 1, v1);
          }
        }
      }
    }
  }
}

// ---------------------------------------------------------------------------
// Launcher
// ---------------------------------------------------------------------------
extern "C" void kernel_launch(void* const* d_in, const int* in_sizes, int n_in,
                              void* d_out, int out_size)
{
  const float* node      = (const float*)d_in[0];
  const float* edge      = (const float*)d_in[1];
  const float* cyc       = (const float*)d_in[2];
  const float* ne_lift_W = (const float*)d_in[3];
  const float* ne_l1_W   = (const float*)d_in[4];
  const float* ne_l2_W   = (const float*)d_in[5];
  const float* ec_lift_W = (const float*)d_in[6];
  const float* ec_l1_W   = (const float*)d_in[7];
  const float* ec_l2_W   = (const float*)d_in[8];
  const float* mlp_W     = (const float*)d_in[9];
  const float* eps1      = (const float*)d_in[10];
  const float* eps2      = (const float*)d_in[11];
  const float* e11       = (const float*)d_in[12];
  const float* e12       = (const float*)d_in[13];
  const float* e2        = (const float*)d_in[14];
  const int*   edge_nodes= (const int*)  d_in[15];
  const int*   c5        = (const int*)  d_in[16];
  const int*   c6        = (const int*)  d_in[17];

  const int N  = in_sizes[0]  / 128;
  const int E  = in_sizes[1]  / 128;
  const int C5 = in_sizes[16] / 5;
  const int C6 = in_sizes[17] / 6;
  const int R  = 5*C5 + 6*C6;
  float* out = (float*)d_out;

  float *edge_h, *S, *lvl_ne, *lvl, *lvl_ec, *inter, *eo1, *eo2, *Wt;
  int *ei, *ep, *rn, *cid;
  cudaGetSymbolAddress((void**)&edge_h, g_edge_h);
  cudaGetSymbolAddress((void**)&S,      g_S);
  cudaGetSymbolAddress((void**)&lvl_ne, g_lvl_ne);
  cudaGetSymbolAddress((void**)&lvl,    g_lvl);
  cudaGetSymbolAddress((void**)&lvl_ec, g_lvl_ec);
  cudaGetSymbolAddress((void**)&inter,  g_inter);
  cudaGetSymbolAddress((void**)&eo1,    g_eo1);
  cudaGetSymbolAddress((void**)&eo2,    g_eo2);
  cudaGetSymbolAddress((void**)&Wt,     g_Wt);
  cudaGetSymbolAddress((void**)&ei,  g_ei);
  cudaGetSymbolAddress((void**)&ep,  g_ep);
  cudaGetSymbolAddress((void**)&rn,  g_rn);
  cudaGetSymbolAddress((void**)&cid, g_cid);

  cudaMemsetAsync(lvl_ne, 0, (size_t)N*128*sizeof(float), 0);
  cudaMemsetAsync(lvl_ec, 0, (size_t)E*128*sizeof(float), 0);
  cudaMemsetAsync(inter,  0, (size_t)E*256*sizeof(float), 0);

  // transpose weights -> Wt[n][k]
  dim3 tb(32, 8);
  transpose_k<<<dim3(4,  8), tb>>>(ne_l1_W,   Wt + WT_NE_L1,   256, 128);
  transpose_k<<<dim3(4,  4), tb>>>(ne_l2_W,   Wt + WT_NE_L2,   128, 128);
  transpose_k<<<dim3(4,  4), tb>>>(ne_lift_W, Wt + WT_NE_LIFT, 128, 128);
  transpose_k<<<dim3(4, 16), tb>>>(ec_l1_W,   Wt + WT_EC_L1,   512, 128);
  transpose_k<<<dim3(4,  4), tb>>>(ec_l2_W,   Wt + WT_EC_L2,   128, 128);
  transpose_k<<<dim3(8,  8), tb>>>(ec_lift_W, Wt + WT_EC_LIFT, 256, 256);
  transpose_k<<<dim3(4,  8), tb>>>(mlp_W,     Wt + WT_MLP,     256, 128);

  meta_k<<<(R + 255)/256, 256>>>(c5, c6, C5, C6, R, ei, ep, rn, cid);
  sum_k<<<C5 + C6, 128>>>(edge, c5, c6, C5, S);

  // G1: edge_h = relu([node[u]+node[v] | edge] @ ne_l1_W); scatter to lvl_ne
  {
    GemmArgs a{}; a.B = Wt + WT_NE_L1; a.M = E; a.K = 256;
    a.out = edge_h; a.ldo = 128; a.aux = lvl_ne;
    a.a0 = node; a.a1 = edge; a.idx0 = edge_nodes;
    mgemm_k<1><<<dim3(1, (E + 127)/128), 256>>>(a);
  }
  // G2: node_out = relu(((1+eps1)*node + lvl_ne) @ ne_l2_W)
  {
    GemmArgs a{}; a.B = Wt + WT_NE_L2; a.M = N; a.K = 128;
    a.out = out; a.ldo = 128;
    a.a0 = node; a.a1 = lvl_ne; a.sp0 = eps1;
    mgemm_k<2><<<dim3(1, (N + 127)/128), 256>>>(a);
  }
  // G3: edge_out_1 = relu(((1+eps2)*edge_h + node[u]+node[v]) @ ne_lift_W)
  {
    GemmArgs a{}; a.B = Wt + WT_NE_LIFT; a.M = E; a.K = 128;
    a.out = eo1; a.ldo = 128;
    a.a0 = edge_h; a.a1 = node; a.idx0 = edge_nodes; a.sp0 = eps2;
    mgemm_k<3><<<dim3(1, (E + 127)/128), 256>>>(a);
  }
  // G4: lvl = relu([e2c | S | cyc_rep] @ ec_l1_W)
  {
    GemmArgs a{}; a.B = Wt + WT_EC_L1; a.M = R; a.K = 512;
    a.out = lvl; a.ldo = 128;
    a.a0 = edge; a.a1 = S; a.a2 = cyc;
    a.idx0 = ei; a.idx1 = ep; a.idx2 = cid;
    mgemm_k<4><<<dim3(1, (R + 127)/128), 256>>>(a);
  }
  scatter_k<<<R, 128>>>(lvl, cyc, ei, rn, lvl_ec, inter);

  // G5: edge_out_2 = relu(((1+e11)*edge + (1+e12)*lvl_ec) @ ec_l2_W)
  {
    GemmArgs a{}; a.B = Wt + WT_EC_L2; a.M = E; a.K = 128;
    a.out = eo2; a.ldo = 128;
    a.a0 = edge; a.a1 = lvl_ec; a.sp0 = e11; a.sp1 = e12;
    mgemm_k<5><<<dim3(1, (E + 127)/128), 256>>>(a);
  }
  // G6: cycle_out = relu(((1+e2)*lin + lift) @ ec_lift_W)  (N=256 -> grid.x=2)
  {
    GemmArgs a{}; a.B = Wt + WT_EC_LIFT; a.M = R; a.K = 256;
    a.out = out + (size_t)(N + E)*128; a.ldo = 256;
    a.a0 = inter; a.a1 = edge; a.a2 = S;
    a.idx0 = ei; a.idx1 = ep; a.idx2 = cid; a.sp0 = e2;
    mgemm_k<6><<<dim3(2, (R + 127)/128), 256>>>(a);
  }
  // G7: edge_out = relu([eo1 | eo2] @ mlp_W)
  {
    GemmArgs a{}; a.B = Wt + WT_MLP; a.M = E; a.K = 256;
    a.out = out + (size_t)N*128; a.ldo = 128;
    a.a0 = eo1; a.a1 = eo2;
    mgemm_k<7><<<dim3(1, (E + 127)/128), 256>>>(a);
  }
}